// round 13
// baseline (speedup 1.0000x reference)
#include <cuda_runtime.h>
#include <cuda_bf16.h>
#include <cstdint>

// Problem constants
#define NNODES 50000
#define NEDGES 600000
#define IN_DIM 256
#define NH     4
#define HD     128
#define FDIM   (NH*HD)     // 512
#define NEG_SLOPE 0.2f

// ---------------- scratch (static __device__ — no allocations allowed) ----------------
__device__ float g_T[(size_t)NNODES * FDIM];     // h = x@W (per layer)
__device__ float g_el[NNODES * NH];
__device__ float g_er[NNODES * NH];
__device__ float g_EX[(size_t)NH * NEDGES];      // exp(e), head-major [head][edge]
__device__ __nv_bfloat16 g_Ahi[(size_t)NNODES * FDIM];
__device__ __nv_bfloat16 g_Alo[(size_t)NNODES * FDIM];
__device__ __nv_bfloat16 g_Whi0[(size_t)FDIM * IN_DIM];  // W0^T bf16 hi
__device__ __nv_bfloat16 g_Wlo0[(size_t)FDIM * IN_DIM];
__device__ __nv_bfloat16 g_Whi1[(size_t)FDIM * FDIM];    // W1^T bf16 hi
__device__ __nv_bfloat16 g_Wlo1[(size_t)FDIM * FDIM];
// CSR scratch
__device__ int g_deg[NNODES];
__device__ int g_rowptr[NNODES + 1];
__device__ int g_cursor[NNODES];
__device__ int g_csrc[NEDGES];

// ---------------- small utils ----------------
__global__ void zero_int_kernel(int* p, int n) {
    int i = blockIdx.x * blockDim.x + threadIdx.x;
    if (i < n) p[i] = 0;
}

__global__ void hist_kernel(const int* __restrict__ dst, int* __restrict__ deg) {
    int e = blockIdx.x * blockDim.x + threadIdx.x;
    if (e < NEDGES) atomicAdd(&deg[dst[e]], 1);
}

// single-block Hillis-Steele scan over NNODES, emits rowptr (exclusive) + cursor copy
__global__ __launch_bounds__(1024) void scan_kernel(const int* __restrict__ deg,
                                                    int* __restrict__ rowptr,
                                                    int* __restrict__ cursor) {
    __shared__ int sA[1024], sB[1024];
    int tid = threadIdx.x;
    int carry = 0;
    for (int base = 0; base < NNODES; base += 1024) {
        int i = base + tid;
        int v = (i < NNODES) ? deg[i] : 0;
        sA[tid] = v;
        __syncthreads();
        int* in = sA; int* out = sB;
#pragma unroll
        for (int off = 1; off < 1024; off <<= 1) {
            int x = in[tid];
            if (tid >= off) x += in[tid - off];
            out[tid] = x;
            __syncthreads();
            int* t = in; in = out; out = t;
        }
        int incl = in[tid];
        int excl = incl - v;
        if (i < NNODES) { rowptr[i] = carry + excl; cursor[i] = carry + excl; }
        int total = in[1023];
        __syncthreads();
        carry += total;
    }
    if (tid == 0) rowptr[NNODES] = carry;
}

__global__ void scatter_kernel(const int* __restrict__ src, const int* __restrict__ dst,
                               int* __restrict__ cursor, int* __restrict__ csrc) {
    int e = blockIdx.x * blockDim.x + threadIdx.x;
    if (e >= NEDGES) return;
    int pos = atomicAdd(&cursor[dst[e]], 1);
    csrc[pos] = src[e];
}

// ---------------- fp32 -> bf16 hi/lo split (element-wise) ----------------
__global__ void convA_kernel(const float* __restrict__ in,
                             __nv_bfloat16* __restrict__ hi,
                             __nv_bfloat16* __restrict__ lo, size_t n4) {
    size_t i = (size_t)blockIdx.x * blockDim.x + threadIdx.x;
    if (i >= n4) return;
    float4 v = ((const float4*)in)[i];
    __nv_bfloat16 h0 = __float2bfloat16_rn(v.x), h1 = __float2bfloat16_rn(v.y);
    __nv_bfloat16 h2 = __float2bfloat16_rn(v.z), h3 = __float2bfloat16_rn(v.w);
    __nv_bfloat16 l0 = __float2bfloat16_rn(v.x - __bfloat162float(h0));
    __nv_bfloat16 l1 = __float2bfloat16_rn(v.y - __bfloat162float(h1));
    __nv_bfloat16 l2 = __float2bfloat16_rn(v.z - __bfloat162float(h2));
    __nv_bfloat16 l3 = __float2bfloat16_rn(v.w - __bfloat162float(h3));
    ((__nv_bfloat162*)hi)[i * 2 + 0] = __nv_bfloat162(h0, h1);
    ((__nv_bfloat162*)hi)[i * 2 + 1] = __nv_bfloat162(h2, h3);
    ((__nv_bfloat162*)lo)[i * 2 + 0] = __nv_bfloat162(l0, l1);
    ((__nv_bfloat162*)lo)[i * 2 + 1] = __nv_bfloat162(l2, l3);
}

// ---------------- W[K,512] -> W^T[512,K] bf16 hi/lo ----------------
__global__ void convW_kernel(const float* __restrict__ W,
                             __nv_bfloat16* __restrict__ hi,
                             __nv_bfloat16* __restrict__ lo, int K) {
    int idx = blockIdx.x * blockDim.x + threadIdx.x;
    if (idx >= FDIM * K) return;
    int n = idx / K, k = idx - n * K;
    float v = W[(size_t)k * FDIM + n];
    __nv_bfloat16 h = __float2bfloat16_rn(v);
    hi[idx] = h;
    lo[idx] = __float2bfloat16_rn(v - __bfloat162float(h));
}

// ---------------- HMMA GEMM, cp.async 2-stage pipeline, fused el/er epilogue ----------------
// C[M,512] = A[M,K] @ B^T (3-term bf16 hi/lo). grid.x selects head; epilogue computes
// el[n,head] = <C row chunk, al[head]>, er likewise — identical math to a separate pass.
#define MMA_BF16(d, a, b)                                                            \
    asm volatile("mma.sync.aligned.m16n8k16.row.col.f32.bf16.bf16.f32 "              \
        "{%0,%1,%2,%3}, {%4,%5,%6,%7}, {%8,%9}, {%0,%1,%2,%3};"                      \
        : "+f"((d)[0]), "+f"((d)[1]), "+f"((d)[2]), "+f"((d)[3])                     \
        : "r"((a)[0]), "r"((a)[1]), "r"((a)[2]), "r"((a)[3]),                        \
          "r"((b)[0]), "r"((b)[1]))

__device__ __forceinline__ void cp16(uint32_t d, const void* g, int sz) {
    asm volatile("cp.async.cg.shared.global [%0], [%1], 16, %2;" :: "r"(d), "l"(g), "r"(sz));
}
__device__ __forceinline__ void cp_commit() { asm volatile("cp.async.commit_group;" ::: "memory"); }
template <int N>
__device__ __forceinline__ void cp_wait() { asm volatile("cp.async.wait_group %0;" :: "n"(N) : "memory"); }

static constexpr int GS_BUF   = 10240;         // 128 rows * 40 elems * 2B
static constexpr int GS_STAGE = 4 * GS_BUF;    // Ah, Al, Bh, Bl
static constexpr int GS_TOTAL = 2 * GS_STAGE;  // 81920

template <int K>
__global__ __launch_bounds__(256) void hmma_gemm(const __nv_bfloat16* __restrict__ Ahi,
                                                 const __nv_bfloat16* __restrict__ Alo,
                                                 const __nv_bfloat16* __restrict__ Bhi,
                                                 const __nv_bfloat16* __restrict__ Blo,
                                                 float* __restrict__ C, int M,
                                                 const float* __restrict__ alv,
                                                 const float* __restrict__ arv,
                                                 float* __restrict__ el,
                                                 float* __restrict__ er) {
    extern __shared__ char smem[];
    uint32_t sbase;
    asm("{ .reg .u64 t; cvta.to.shared.u64 t, %1; cvt.u32.u64 %0, t; }" : "=r"(sbase) : "l"(smem));

    int tid = threadIdx.x;
    int lane = tid & 31;
    int wid = tid >> 5;
    int wr = wid & 3;
    int wc = wid >> 2;
    int gr4 = lane >> 2;
    int tig = lane & 3;

    int row0 = blockIdx.y * 128;
    int col0 = blockIdx.x * 128;     // == head * HD

    const __nv_bfloat16* gsrc[4] = { Ahi, Alo, Bhi, Blo };

    auto load_stage = [&](int kt, int st) {
        int k0 = kt * 32;
#pragma unroll
        for (int j = 0; j < 8; j++) {
            const int buf = j >> 1;
            int rem = (j & 1) * 256 + tid;
            int r = rem >> 2, c = (rem & 3) * 8;
            uint32_t doff = sbase + st * GS_STAGE + buf * GS_BUF + (r * 40 + c) * 2;
            int gr = (buf < 2) ? (row0 + r) : (col0 + r);
            const void* gp = gsrc[buf] + (size_t)gr * K + k0 + c;
            int sz = (buf < 2 && gr >= M) ? 0 : 16;
            cp16(doff, gp, sz);
        }
    };

    float acc[2][8][4];
#pragma unroll
    for (int mt = 0; mt < 2; mt++)
#pragma unroll
        for (int nt = 0; nt < 8; nt++)
#pragma unroll
            for (int q = 0; q < 4; q++) acc[mt][nt][q] = 0.f;

    const int NK = K / 32;
    load_stage(0, 0);
    cp_commit();

#pragma unroll 1
    for (int kt = 0; kt < NK; kt++) {
        int st = kt & 1;
        if (kt + 1 < NK) { load_stage(kt + 1, st ^ 1); cp_commit(); cp_wait<1>(); }
        else            { cp_wait<0>(); }
        __syncthreads();

        const __nv_bfloat16* pAh = (const __nv_bfloat16*)(smem + st * GS_STAGE);
        const __nv_bfloat16* pAl = (const __nv_bfloat16*)(smem + st * GS_STAGE + GS_BUF);
        const __nv_bfloat16* pBh = (const __nv_bfloat16*)(smem + st * GS_STAGE + 2 * GS_BUF);
        const __nv_bfloat16* pBl = (const __nv_bfloat16*)(smem + st * GS_STAGE + 3 * GS_BUF);

#pragma unroll
        for (int ks = 0; ks < 2; ks++) {
            int kb = ks * 16;
            uint32_t ah[2][4], al4[2][4];
#pragma unroll
            for (int mt = 0; mt < 2; mt++) {
                int mr = wr * 32 + mt * 16 + gr4;
                ah[mt][0] = *(const uint32_t*)(pAh + mr * 40 + kb + tig * 2);
                ah[mt][1] = *(const uint32_t*)(pAh + (mr + 8) * 40 + kb + tig * 2);
                ah[mt][2] = *(const uint32_t*)(pAh + mr * 40 + kb + 8 + tig * 2);
                ah[mt][3] = *(const uint32_t*)(pAh + (mr + 8) * 40 + kb + 8 + tig * 2);
                al4[mt][0] = *(const uint32_t*)(pAl + mr * 40 + kb + tig * 2);
                al4[mt][1] = *(const uint32_t*)(pAl + (mr + 8) * 40 + kb + tig * 2);
                al4[mt][2] = *(const uint32_t*)(pAl + mr * 40 + kb + 8 + tig * 2);
                al4[mt][3] = *(const uint32_t*)(pAl + (mr + 8) * 40 + kb + 8 + tig * 2);
            }
#pragma unroll
            for (int nt = 0; nt < 8; nt++) {
                int nc = wc * 64 + nt * 8 + gr4;
                uint32_t bh[2], bl[2];
                bh[0] = *(const uint32_t*)(pBh + nc * 40 + kb + tig * 2);
                bh[1] = *(const uint32_t*)(pBh + nc * 40 + kb + 8 + tig * 2);
                bl[0] = *(const uint32_t*)(pBl + nc * 40 + kb + tig * 2);
                bl[1] = *(const uint32_t*)(pBl + nc * 40 + kb + 8 + tig * 2);
#pragma unroll
                for (int mt = 0; mt < 2; mt++) {
                    MMA_BF16(acc[mt][nt], ah[mt], bh);
                    MMA_BF16(acc[mt][nt], ah[mt], bl);
                    MMA_BF16(acc[mt][nt], al4[mt], bh);
                }
            }
        }
        __syncthreads();
    }

    // ---- store C + fused el/er partials ----
    const float* alh = alv + col0;   // head's 128-vector
    const float* arh = arv + col0;
    float pel[4] = {0.f, 0.f, 0.f, 0.f};   // rows: [mt*2 + half], half0=r0, half1=r0+8
    float per[4] = {0.f, 0.f, 0.f, 0.f};

#pragma unroll
    for (int mt = 0; mt < 2; mt++) {
        int r0 = row0 + wr * 32 + mt * 16 + gr4;
#pragma unroll
        for (int nt = 0; nt < 8; nt++) {
            int lc = wc * 64 + nt * 8 + tig * 2;       // local col in head
            float a0 = __ldg(alh + lc), a1 = __ldg(alh + lc + 1);
            float b0 = __ldg(arh + lc), b1 = __ldg(arh + lc + 1);
            pel[mt * 2 + 0] += acc[mt][nt][0] * a0 + acc[mt][nt][1] * a1;
            per[mt * 2 + 0] += acc[mt][nt][0] * b0 + acc[mt][nt][1] * b1;
            pel[mt * 2 + 1] += acc[mt][nt][2] * a0 + acc[mt][nt][3] * a1;
            per[mt * 2 + 1] += acc[mt][nt][2] * b0 + acc[mt][nt][3] * b1;

            int cc = col0 + lc;
            if (r0 < M)
                *(float2*)(C + (size_t)r0 * FDIM + cc) = make_float2(acc[mt][nt][0], acc[mt][nt][1]);
            if (r0 + 8 < M)
                *(float2*)(C + (size_t)(r0 + 8) * FDIM + cc) = make_float2(acc[mt][nt][2], acc[mt][nt][3]);
        }
    }
    // reduce over tig (lanes 0..3 within each gr4 group)
#pragma unroll
    for (int j = 0; j < 4; j++) {
#pragma unroll
        for (int o = 1; o < 4; o <<= 1) {
            pel[j] += __shfl_xor_sync(0xFFFFFFFFu, pel[j], o);
            per[j] += __shfl_xor_sync(0xFFFFFFFFu, per[j], o);
        }
    }
    // stage per-wc partials in (now dead) smem: sEl[wc][128], sEr[wc][128]
    float* sEl = (float*)smem;
    float* sEr = sEl + 256;
    if (tig == 0) {
#pragma unroll
        for (int j = 0; j < 4; j++) {
            int rl = wr * 32 + (j >> 1) * 16 + gr4 + (j & 1) * 8;
            sEl[wc * 128 + rl] = pel[j];
            sEr[wc * 128 + rl] = per[j];
        }
    }
    __syncthreads();
    if (tid < 128) {
        int gr = row0 + tid;
        if (gr < M) {
            el[(size_t)gr * NH + blockIdx.x] = sEl[tid] + sEl[128 + tid];
            er[(size_t)gr * NH + blockIdx.x] = sEr[tid] + sEr[128 + tid];
        }
    }
}

__device__ __forceinline__ float lrelu_exp(float v) {
    v = v > 0.f ? v : NEG_SLOPE * v;
    return __expf(v);
}

// ---------------- CSR aggregation: one warp per (node, head) ----------------
template <int MODE>
__global__ __launch_bounds__(256) void agg_kernel(const int* __restrict__ rowptr,
                                                  const int* __restrict__ csrc,
                                                  const float* __restrict__ el,
                                                  const float* __restrict__ er,
                                                  const float* __restrict__ T,
                                                  float* __restrict__ EX,
                                                  __nv_bfloat16* __restrict__ Ahi,
                                                  __nv_bfloat16* __restrict__ Alo,
                                                  float* __restrict__ out) {
    __shared__ float sred[2][FDIM];   // MODE 1 only
    int gw = (blockIdx.x * blockDim.x + threadIdx.x) >> 5;
    int lane = threadIdx.x & 31;
    int t = gw >> 2;
    int head = gw & 3;

    if (t < NNODES) {
        int rs = rowptr[t], re = rowptr[t + 1];
        float er_own = __ldg(er + (size_t)t * NH + head);
        float* EXp = EX + (size_t)head * NEDGES;

        // phase 1: exp per edge (own head), coalesced store, denom reduce
        float d = 0.f;
        for (int i = rs + lane; i < re; i += 32) {
            int s = __ldg(csrc + i);
            float ex = lrelu_exp(__ldg(el + (size_t)s * NH + head) + er_own);
            EXp[i] = ex;
            d += ex;
        }
#pragma unroll
        for (int o = 16; o > 0; o >>= 1) d += __shfl_xor_sync(0xFFFFFFFFu, d, o);
        float inv_dn = (d > 0.f) ? (1.f / d) : 0.f;
        __syncwarp();

        // phase 2: acc over edges; lane owns features [head*128 + lane*4, +4)
        float4 acc = make_float4(0.f, 0.f, 0.f, 0.f);
        const float* Tb = T + head * HD + lane * 4;
        for (int i0 = rs; i0 < re; i0 += 32) {
            int s_l = (i0 + lane < re) ? __ldg(csrc + i0 + lane) : 0;
            int cnt = min(32, re - i0);
            int j = 0;
            for (; j + 1 < cnt; j += 2) {
                int s0 = __shfl_sync(0xFFFFFFFFu, s_l, j);
                int s1 = __shfl_sync(0xFFFFFFFFu, s_l, j + 1);
                float a0 = EXp[i0 + j] * inv_dn;
                float a1 = EXp[i0 + j + 1] * inv_dn;
                float4 v0 = *(const float4*)(Tb + (size_t)s0 * FDIM);
                float4 v1 = *(const float4*)(Tb + (size_t)s1 * FDIM);
                acc.x += a0 * v0.x + a1 * v1.x;
                acc.y += a0 * v0.y + a1 * v1.y;
                acc.z += a0 * v0.z + a1 * v1.z;
                acc.w += a0 * v0.w + a1 * v1.w;
            }
            if (j < cnt) {
                int s0 = __shfl_sync(0xFFFFFFFFu, s_l, j);
                float a0 = EXp[i0 + j] * inv_dn;
                float4 v0 = *(const float4*)(Tb + (size_t)s0 * FDIM);
                acc.x += a0 * v0.x;
                acc.y += a0 * v0.y;
                acc.z += a0 * v0.z;
                acc.w += a0 * v0.w;
            }
        }

        acc.x = fmaxf(acc.x, 0.f);
        acc.y = fmaxf(acc.y, 0.f);
        acc.z = fmaxf(acc.z, 0.f);
        acc.w = fmaxf(acc.w, 0.f);

        if (MODE == 0) {
            __nv_bfloat16 h0 = __float2bfloat16_rn(acc.x), h1 = __float2bfloat16_rn(acc.y);
            __nv_bfloat16 h2 = __float2bfloat16_rn(acc.z), h3 = __float2bfloat16_rn(acc.w);
            __nv_bfloat16 l0 = __float2bfloat16_rn(acc.x - __bfloat162float(h0));
            __nv_bfloat16 l1 = __float2bfloat16_rn(acc.y - __bfloat162float(h1));
            __nv_bfloat16 l2 = __float2bfloat16_rn(acc.z - __bfloat162float(h2));
            __nv_bfloat16 l3 = __float2bfloat16_rn(acc.w - __bfloat162float(h3));
            size_t off = (size_t)t * FDIM + head * HD + lane * 4;
            __nv_bfloat162 hh0(h0, h1), hh1(h2, h3), ll0(l0, l1), ll1(l2, l3);
            uint32_t ph0 = *(uint32_t*)&hh0, ph1 = *(uint32_t*)&hh1;
            uint32_t pl0 = *(uint32_t*)&ll0, pl1 = *(uint32_t*)&ll1;
            *(uint2*)(Ahi + off) = make_uint2(ph0, ph1);
            *(uint2*)(Alo + off) = make_uint2(pl0, pl1);
        } else {
            int nl = (threadIdx.x >> 5) >> 2;   // node slot in block (0/1)
            *(float4*)&sred[nl][head * HD + lane * 4] = acc;
        }
    }

    if (MODE == 1) {
        __syncthreads();
        int tid = threadIdx.x;
        int nl = tid >> 7;
        int dch = tid & 127;
        int node = blockIdx.x * 2 + nl;
        if (node < NNODES) {
            float v = sred[nl][dch] + sred[nl][HD + dch] + sred[nl][2 * HD + dch] + sred[nl][3 * HD + dch];
            out[(size_t)node * HD + dch] = 0.25f * v;
        }
    }
}

// ---------------- launch ----------------
extern "C" void kernel_launch(void* const* d_in, const int* in_sizes, int n_in,
                              void* d_out, int out_size) {
    const float* x   = (const float*)d_in[0];
    const int*   src = (const int*)d_in[1];
    const int*   dst = (const int*)d_in[2];
    const float* W0  = (const float*)d_in[3];
    const float* al0 = (const float*)d_in[4];
    const float* ar0 = (const float*)d_in[5];
    const float* W1  = (const float*)d_in[6];
    const float* al1 = (const float*)d_in[7];
    const float* ar1 = (const float*)d_in[8];
    float* out = (float*)d_out;

    float *T, *el, *er, *EX;
    __nv_bfloat16 *Ahi, *Alo, *Whi0, *Wlo0, *Whi1, *Wlo1;
    int *deg, *rowptr, *cursor, *csrc;
    cudaGetSymbolAddress((void**)&T, g_T);
    cudaGetSymbolAddress((void**)&el, g_el);
    cudaGetSymbolAddress((void**)&er, g_er);
    cudaGetSymbolAddress((void**)&EX, g_EX);
    cudaGetSymbolAddress((void**)&Ahi, g_Ahi);
    cudaGetSymbolAddress((void**)&Alo, g_Alo);
    cudaGetSymbolAddress((void**)&Whi0, g_Whi0);
    cudaGetSymbolAddress((void**)&Wlo0, g_Wlo0);
    cudaGetSymbolAddress((void**)&Whi1, g_Whi1);
    cudaGetSymbolAddress((void**)&Wlo1, g_Wlo1);
    cudaGetSymbolAddress((void**)&deg, g_deg);
    cudaGetSymbolAddress((void**)&rowptr, g_rowptr);
    cudaGetSymbolAddress((void**)&cursor, g_cursor);
    cudaGetSymbolAddress((void**)&csrc, g_csrc);

    cudaFuncSetAttribute(hmma_gemm<IN_DIM>, cudaFuncAttributeMaxDynamicSharedMemorySize, GS_TOTAL);
    cudaFuncSetAttribute(hmma_gemm<FDIM>,   cudaFuncAttributeMaxDynamicSharedMemorySize, GS_TOTAL);

    dim3 gemmGrid(FDIM / 128, (NNODES + 127) / 128);   // (4, 391)
    int aggBlocks  = (NNODES * NH + 7) / 8;             // warp per (node, head)
    int edgeBlocks = (NEDGES + 255) / 256;

    // ---------------- host-resource cache (streams/events created once per process;
    // device work per call is identical and deterministic) ----------------
    static cudaStream_t s1 = nullptr, s2 = nullptr;
    static cudaEvent_t ev0 = nullptr, evCsr = nullptr, evW = nullptr;
    if (s1 == nullptr) {
        cudaStreamCreateWithFlags(&s1, cudaStreamNonBlocking);
        cudaStreamCreateWithFlags(&s2, cudaStreamNonBlocking);
        cudaEventCreateWithFlags(&ev0, cudaEventDisableTiming);
        cudaEventCreateWithFlags(&evCsr, cudaEventDisableTiming);
        cudaEventCreateWithFlags(&evW, cudaEventDisableTiming);
    }

    // ---------------- fork: CSR build (s1) + weight conversion (s2) ----------------
    cudaEventRecord(ev0, 0);
    cudaStreamWaitEvent(s1, ev0, 0);
    cudaStreamWaitEvent(s2, ev0, 0);

    zero_int_kernel<<<(NNODES + 255) / 256, 256, 0, s1>>>(deg, NNODES);
    hist_kernel<<<edgeBlocks, 256, 0, s1>>>(dst, deg);
    scan_kernel<<<1, 1024, 0, s1>>>(deg, rowptr, cursor);
    scatter_kernel<<<edgeBlocks, 256, 0, s1>>>(src, dst, cursor, csrc);
    cudaEventRecord(evCsr, s1);

    convW_kernel<<<(FDIM * IN_DIM + 255) / 256, 256, 0, s2>>>(W0, Whi0, Wlo0, IN_DIM);
    convW_kernel<<<(FDIM * FDIM + 255) / 256, 256, 0, s2>>>(W1, Whi1, Wlo1, FDIM);
    cudaEventRecord(evW, s2);

    // ---------------- layer 0 (main stream) ----------------
    {
        size_t n4 = (size_t)NNODES * IN_DIM / 4;
        convA_kernel<<<(unsigned)((n4 + 255) / 256), 256>>>(x, Ahi, Alo, n4);
    }
    cudaStreamWaitEvent(0, evW, 0);
    hmma_gemm<IN_DIM><<<gemmGrid, 256, GS_TOTAL>>>(Ahi, Alo, Whi0, Wlo0, T, NNODES,
                                                   al0, ar0, el, er);
    cudaStreamWaitEvent(0, evCsr, 0);
    agg_kernel<0><<<aggBlocks, 256>>>(rowptr, csrc, el, er, T, EX, Ahi, Alo, nullptr);

    // ---------------- layer 1 ----------------
    hmma_gemm<FDIM><<<gemmGrid, 256, GS_TOTAL>>>(Ahi, Alo, Whi1, Wlo1, T, NNODES,
                                                 al1, ar1, el, er);
    agg_kernel<1><<<aggBlocks, 256>>>(rowptr, csrc, el, er, T, EX, nullptr, nullptr, out);
}